// round 13
// baseline (speedup 1.0000x reference)
#include <cuda_runtime.h>
#include <cuda_bf16.h>
#include <math.h>
#include <stdint.h>

#define B_  2
#define T_  2048
#define D_  2048
#define H_  16
#define G_  4
#define HD_ 128

// ---------------- scratch (static device globals; no allocation) ----------------
__device__ float g_qg[(size_t)B_ * T_ * H_ * 2 * HD_];   // fp32 q+gate from bf16x3 GEMM
__device__ float g_q [(size_t)B_ * H_ * T_ * HD_];       // tf32 bits for flash
__device__ float g_k [(size_t)B_ * T_ * G_ * HD_];       // tf32 bits for flash
__device__ float g_v [(size_t)B_ * T_ * G_ * HD_];       // tf32 bits for flash
// split-bf16 operands
__device__ __nv_bfloat16 g_xh [(size_t)B_ * T_ * D_];
__device__ __nv_bfloat16 g_xl [(size_t)B_ * T_ * D_];
__device__ __nv_bfloat16 g_wqh[(size_t)2 * H_ * HD_ * D_];  // [N,K] transposed
__device__ __nv_bfloat16 g_wql[(size_t)2 * H_ * HD_ * D_];
__device__ __nv_bfloat16 g_wkh[(size_t)G_ * HD_ * D_];
__device__ __nv_bfloat16 g_wkl[(size_t)G_ * HD_ * D_];
__device__ __nv_bfloat16 g_wvh[(size_t)G_ * HD_ * D_];
__device__ __nv_bfloat16 g_wvl[(size_t)G_ * HD_ * D_];
__device__ __nv_bfloat16 g_woh[(size_t)D_ * H_ * HD_];      // [N=D, K=H*HD]
__device__ __nv_bfloat16 g_wol[(size_t)D_ * H_ * HD_];
__device__ __nv_bfloat16 g_ah [(size_t)B_ * T_ * H_ * HD_]; // gated attn hi
__device__ __nv_bfloat16 g_al [(size_t)B_ * T_ * H_ * HD_]; // gated attn lo

// ---------------- helpers ----------------
__device__ __forceinline__ unsigned f2tf32(float x) {
    unsigned r;
    asm("cvt.rna.tf32.f32 %0, %1;" : "=r"(r) : "f"(x));
    return r;
}
__device__ __forceinline__ void split1(float v, __nv_bfloat16& h, __nv_bfloat16& l) {
    h = __float2bfloat16(v);
    l = __float2bfloat16(v - __bfloat162float(h));
}
__device__ __forceinline__ void mma_tf32(float* c, unsigned a0, unsigned a1, unsigned a2,
                                         unsigned a3, unsigned b0, unsigned b1) {
    asm volatile(
        "mma.sync.aligned.m16n8k8.row.col.f32.tf32.tf32.f32 "
        "{%0,%1,%2,%3}, {%4,%5,%6,%7}, {%8,%9}, {%0,%1,%2,%3};\n"
        : "+f"(c[0]), "+f"(c[1]), "+f"(c[2]), "+f"(c[3])
        : "r"(a0), "r"(a1), "r"(a2), "r"(a3), "r"(b0), "r"(b1));
}
__device__ __forceinline__ void mma_bf16(float* c, unsigned a0, unsigned a1, unsigned a2,
                                         unsigned a3, unsigned b0, unsigned b1) {
    asm volatile(
        "mma.sync.aligned.m16n8k16.row.col.f32.bf16.bf16.f32 "
        "{%0,%1,%2,%3}, {%4,%5,%6,%7}, {%8,%9}, {%0,%1,%2,%3};\n"
        : "+f"(c[0]), "+f"(c[1]), "+f"(c[2]), "+f"(c[3])
        : "r"(a0), "r"(a1), "r"(a2), "r"(a3), "r"(b0), "r"(b1));
}

__global__ void cvt_tf32(const float* __restrict__ in, float* __restrict__ out, int n4) {
    int i = blockIdx.x * blockDim.x + threadIdx.x;
    if (i < n4) {
        float4 v = ((const float4*)in)[i];
        uint4 o;
        o.x = f2tf32(v.x); o.y = f2tf32(v.y); o.z = f2tf32(v.z); o.w = f2tf32(v.w);
        ((uint4*)out)[i] = o;
    }
}

// split (no transpose): x -> xh, xl
__global__ void cvt_split(const float* __restrict__ in, __nv_bfloat16* __restrict__ hi,
                          __nv_bfloat16* __restrict__ lo, int n4) {
    int i = blockIdx.x * blockDim.x + threadIdx.x;
    if (i < n4) {
        float4 v = ((const float4*)in)[i];
        float vv[4] = {v.x, v.y, v.z, v.w};
        unsigned hp[2], lp[2];
#pragma unroll
        for (int p = 0; p < 2; p++) {
            __nv_bfloat16 h0, l0, h1, l1;
            split1(vv[2 * p], h0, l0);
            split1(vv[2 * p + 1], h1, l1);
            hp[p] = ((unsigned)__bfloat16_as_ushort(h1) << 16) | __bfloat16_as_ushort(h0);
            lp[p] = ((unsigned)__bfloat16_as_ushort(l1) << 16) | __bfloat16_as_ushort(l0);
        }
        ((uint2*)hi)[i] = make_uint2(hp[0], hp[1]);
        ((uint2*)lo)[i] = make_uint2(lp[0], lp[1]);
    }
}

// W[K,N] -> Th/Tl[N,K] (transpose + split)
__global__ void cvt_split_t(const float* __restrict__ W, __nv_bfloat16* __restrict__ Th,
                            __nv_bfloat16* __restrict__ Tl, int K, int N) {
    __shared__ float t[32][33];
    int n0 = blockIdx.x * 32, k0 = blockIdx.y * 32;
    int tx = threadIdx.x, ty = threadIdx.y;  // (32,8)
#pragma unroll
    for (int i = 0; i < 4; i++)
        t[ty + 8 * i][tx] = W[(size_t)(k0 + ty + 8 * i) * N + n0 + tx];
    __syncthreads();
#pragma unroll
    for (int i = 0; i < 4; i++) {
        float v = t[tx][ty + 8 * i];
        __nv_bfloat16 h, l;
        split1(v, h, l);
        size_t o = (size_t)(n0 + ty + 8 * i) * K + k0 + tx;
        Th[o] = h;
        Tl[o] = l;
    }
}

// ---------------- bf16 3-pass GEMM: C[M,N] = (Ah+Al)[M,K] @ (Bh+Bl)[N,K]^T ----------------
// R11-proven skeleton: 128x128 tile, 256 thr, 8 warps (64x32), double-buffered cp.async,
// occupancy 2. BK=32 bf16 per stage; word-pitch 20 (proven conflict-free).
#define WPW 20                      // words per row (32 bf16 = 16 words + 4 pad)
#define TILE_W (128 * WPW)          // words per tile
#define GB_SMEM (2 * 4 * TILE_W * 4)  // 2 bufs x 4 tiles x words x 4B = 81920

__device__ __forceinline__ void cp16w(unsigned* smem_dst, const void* gsrc) {
    unsigned sa = (unsigned)__cvta_generic_to_shared(smem_dst);
    asm volatile("cp.async.cg.shared.global [%0], [%1], 16;\n" :: "r"(sa), "l"(gsrc));
}

__global__ __launch_bounds__(256, 2) void gemm_bf16(
        const __nv_bfloat16* __restrict__ Ah, const __nv_bfloat16* __restrict__ Al,
        const __nv_bfloat16* __restrict__ Bh, const __nv_bfloat16* __restrict__ Bl,
        float* __restrict__ C, int M, int N, int K) {
    extern __shared__ unsigned dsmw[];

    int tid  = threadIdx.x;
    int lane = tid & 31;
    int warp = tid >> 5;
    int wm = (warp & 1) * 64;
    int wn = (warp >> 1) * 32;
    int bx = blockIdx.x, by = blockIdx.y;

    const __nv_bfloat16* srcs[4] = {
        Ah + (size_t)by * 128 * K, Al + (size_t)by * 128 * K,
        Bh + (size_t)bx * 128 * K, Bl + (size_t)bx * 128 * K };

    float acc[4][4][4];
#pragma unroll
    for (int i = 0; i < 4; i++)
#pragma unroll
        for (int j = 0; j < 4; j++)
#pragma unroll
            for (int c = 0; c < 4; c++) acc[i][j][c] = 0.f;

    int nk = K / 32;

    // chunk id -> (tile, row, chunk): 4 tiles x 128 rows x 4 chunks(16B) = 2048, 8/thread
    // prologue
    {
        unsigned* base = dsmw;
#pragma unroll
        for (int j = 0; j < 8; j++) {
            int id = tid + 256 * j;
            int tI = id >> 9, r = (id >> 2) & 127, c = id & 3;
            cp16w(base + tI * TILE_W + r * WPW + c * 4, srcs[tI] + (size_t)r * K + c * 8);
        }
        asm volatile("cp.async.commit_group;\n");
    }

    int buf = 0;
    for (int kt = 0; kt < nk; kt++) {
        asm volatile("cp.async.wait_group 0;\n");
        __syncthreads();

        if (kt + 1 < nk) {
            int kb = (kt + 1) * 32;
            unsigned* base = dsmw + (buf ^ 1) * 4 * TILE_W;
#pragma unroll
            for (int j = 0; j < 8; j++) {
                int id = tid + 256 * j;
                int tI = id >> 9, r = (id >> 2) & 127, c = id & 3;
                cp16w(base + tI * TILE_W + r * WPW + c * 4, srcs[tI] + (size_t)r * K + kb + c * 8);
            }
        }
        asm volatile("cp.async.commit_group;\n");

        const unsigned* Ahw = dsmw + buf * 4 * TILE_W;
        const unsigned* Alw = Ahw + TILE_W;
        const unsigned* Bhw = Alw + TILE_W;
        const unsigned* Blw = Bhw + TILE_W;
        int r  = lane >> 2;
        int kc = lane & 3;
#pragma unroll
        for (int ks = 0; ks < 2; ks++) {
            int k0 = ks * 8;  // word offset of this k16 step
            unsigned ah[4][4], al[4][4];
#pragma unroll
            for (int mf = 0; mf < 4; mf++) {
                int m = wm + mf * 16;
                ah[mf][0] = Ahw[(m + r)     * WPW + k0 + kc];
                ah[mf][1] = Ahw[(m + r + 8) * WPW + k0 + kc];
                ah[mf][2] = Ahw[(m + r)     * WPW + k0 + kc + 4];
                ah[mf][3] = Ahw[(m + r + 8) * WPW + k0 + kc + 4];
                al[mf][0] = Alw[(m + r)     * WPW + k0 + kc];
                al[mf][1] = Alw[(m + r + 8) * WPW + k0 + kc];
                al[mf][2] = Alw[(m + r)     * WPW + k0 + kc + 4];
                al[mf][3] = Alw[(m + r + 8) * WPW + k0 + kc + 4];
            }
            unsigned bh[4][2], bl[4][2];
#pragma unroll
            for (int nf = 0; nf < 4; nf++) {
                int n = wn + nf * 8;
                bh[nf][0] = Bhw[(n + r) * WPW + k0 + kc];
                bh[nf][1] = Bhw[(n + r) * WPW + k0 + kc + 4];
                bl[nf][0] = Blw[(n + r) * WPW + k0 + kc];
                bl[nf][1] = Blw[(n + r) * WPW + k0 + kc + 4];
            }
#pragma unroll
            for (int mf = 0; mf < 4; mf++)
#pragma unroll
                for (int nf = 0; nf < 4; nf++) {
                    mma_bf16(acc[mf][nf], ah[mf][0], ah[mf][1], ah[mf][2], ah[mf][3],
                             bh[nf][0], bh[nf][1]);
                    mma_bf16(acc[mf][nf], ah[mf][0], ah[mf][1], ah[mf][2], ah[mf][3],
                             bl[nf][0], bl[nf][1]);
                    mma_bf16(acc[mf][nf], al[mf][0], al[mf][1], al[mf][2], al[mf][3],
                             bh[nf][0], bh[nf][1]);
                }
        }
        buf ^= 1;
    }

    int r  = lane >> 2;
    int cc = (lane & 3) * 2;
#pragma unroll
    for (int mf = 0; mf < 4; mf++) {
#pragma unroll
        for (int nf = 0; nf < 4; nf++) {
            size_t row0 = (size_t)(by * 128 + wm + mf * 16 + r);
            int col = bx * 128 + wn + nf * 8 + cc;
            *(float2*)&C[row0 * N + col]       = make_float2(acc[mf][nf][0], acc[mf][nf][1]);
            *(float2*)&C[(row0 + 8) * N + col] = make_float2(acc[mf][nf][2], acc[mf][nf][3]);
        }
    }
}

// ---------------- Q: RMSNorm + RoPE + scale -> tf32 bits ----------------
__global__ void qnorm_rope(const float* __restrict__ qg, float* __restrict__ qout,
                           const float* __restrict__ w, const float* __restrict__ cs,
                           const float* __restrict__ sn) {
    int t = blockIdx.x;
    int bh = blockIdx.y;
    int b = bh >> 4, h = bh & 15;
    int i = threadIdx.x;  // 128

    const float* row = qg + (((size_t)(b * T_ + t) * H_ + h) * 2 * HD_);
    float v = row[i];

    float ss = v * v;
#pragma unroll
    for (int o = 16; o > 0; o >>= 1) ss += __shfl_xor_sync(0xffffffffu, ss, o);
    __shared__ float warpsum[4];
    __shared__ float normed[HD_];
    if ((i & 31) == 0) warpsum[i >> 5] = ss;
    __syncthreads();
    float tot = warpsum[0] + warpsum[1] + warpsum[2] + warpsum[3];
    float rms = rsqrtf(tot * (1.0f / HD_) + 1e-6f);
    float xv = v * rms * w[i];
    normed[i] = xv;
    __syncthreads();
    float rot = (i < 64) ? -normed[i + 64] : normed[i - 64];
    float o = (xv * cs[t * HD_ + i] + rot * sn[t * HD_ + i]) * 0.08838834764831845f;
    ((unsigned*)qout)[(((size_t)(b * H_ + h) * T_) + t) * HD_ + i] = f2tf32(o);
}

// ---------------- K: RMSNorm + RoPE -> tf32 bits (in place) ----------------
__global__ void knorm_rope(float* __restrict__ kbuf, const float* __restrict__ w,
                           const float* __restrict__ cs, const float* __restrict__ sn) {
    int t = blockIdx.x;
    int bg = blockIdx.y;
    int b = bg >> 2, g = bg & 3;
    int i = threadIdx.x;

    size_t base = ((size_t)(b * T_ + t) * G_ + g) * HD_;
    float v = kbuf[base + i];

    float ss = v * v;
#pragma unroll
    for (int o = 16; o > 0; o >>= 1) ss += __shfl_xor_sync(0xffffffffu, ss, o);
    __shared__ float warpsum[4];
    __shared__ float normed[HD_];
    if ((i & 31) == 0) warpsum[i >> 5] = ss;
    __syncthreads();
    float tot = warpsum[0] + warpsum[1] + warpsum[2] + warpsum[3];
    float rms = rsqrtf(tot * (1.0f / HD_) + 1e-6f);
    float xv = v * rms * w[i];
    normed[i] = xv;
    __syncthreads();
    float rot = (i < 64) ? -normed[i + 64] : normed[i - 64];
    ((unsigned*)kbuf)[base + i] = f2tf32(xv * cs[t * HD_ + i] + rot * sn[t * HD_ + i]);
}

// ---------------- causal GQA flash attention on tf32 tensor cores (R11-proven) ----------------
#define QP 132
#define VP 136
#define SP 68
#define FLASH_SMEM ((64 * QP * 2 + 64 * VP + 64 * SP * 2 + 3 * 64) * 4)

__global__ __launch_bounds__(256, 1) void flash_tc(
        const float* __restrict__ Q, const float* __restrict__ K,
        const float* __restrict__ V, const float* __restrict__ qg,
        __nv_bfloat16* __restrict__ Oh, __nv_bfloat16* __restrict__ Ol) {
    extern __shared__ float sm[];
    float* Qs   = sm;
    float* Ks   = Qs + 64 * QP;
    float* Vs   = Ks + 64 * QP;
    float* Sh   = Vs + 64 * VP;
    float* Sl   = Sh + 64 * SP;
    float* rowm = Sl + 64 * SP;
    float* rowl = rowm + 64;
    float* ralp = rowl + 64;

    int qt = gridDim.x - 1 - blockIdx.x;
    int bh = blockIdx.y;
    int b = bh >> 4, h = bh & 15;
    int g = h >> 2;
    int tid = threadIdx.x;
    int w = tid >> 5, lane = tid & 31;
    int m0  = (w & 3) * 16;
    int n0s = (w >> 2) * 32;
    int n0d = (w >> 2) * 64;
    int lr = lane >> 2, lc = lane & 3;

    const float* Qb = Q + (((size_t)(b * H_ + h) * T_) + qt * 64) * HD_;
    const float* Kb = K + ((size_t)b * T_ * G_ + g) * HD_;
    const float* Vb = V + ((size_t)b * T_ * G_ + g) * HD_;

    for (int i = tid; i < 64 * 32; i += 256) {
        int r = i >> 5, c4 = (i & 31) * 4;
        *(float4*)&Qs[r * QP + c4] = *(const float4*)(Qb + r * HD_ + c4);
    }
    if (tid < 64) { rowm[tid] = -3e30f; rowl[tid] = 0.f; }

    float o[8][4];
#pragma unroll
    for (int nf = 0; nf < 8; nf++)
#pragma unroll
        for (int c = 0; c < 4; c++) o[nf][c] = 0.f;
    __syncthreads();

    for (int j = 0; j <= qt; j++) {
        const float* Kt = Kb + (size_t)(j * 64) * (G_ * HD_);
        const float* Vt = Vb + (size_t)(j * 64) * (G_ * HD_);
        for (int i = tid; i < 64 * 32; i += 256) {
            int r = i >> 5, c4 = (i & 31) * 4;
            *(float4*)&Ks[r * QP + c4] = *(const float4*)(Kt + (size_t)r * (G_ * HD_) + c4);
            *(float4*)&Vs[r * VP + c4] = *(const float4*)(Vt + (size_t)r * (G_ * HD_) + c4);
        }
        __syncthreads();

        float s[4][4];
#pragma unroll
        for (int nf = 0; nf < 4; nf++)
#pragma unroll
            for (int c = 0; c < 4; c++) s[nf][c] = 0.f;

#pragma unroll
        for (int ks = 0; ks < 16; ks++) {
            int k0 = ks * 8;
            unsigned a0 = __float_as_uint(Qs[(m0 + lr)     * QP + k0 + lc]);
            unsigned a1 = __float_as_uint(Qs[(m0 + lr + 8) * QP + k0 + lc]);
            unsigned a2 = __float_as_uint(Qs[(m0 + lr)     * QP + k0 + lc + 4]);
            unsigned a3 = __float_as_uint(Qs[(m0 + lr + 8) * QP + k0 + lc + 4]);
#pragma unroll
            for (int nf = 0; nf < 4; nf++) {
                int n = n0s + nf * 8;
                unsigned b0 = __float_as_uint(Ks[(n + lr) * QP + k0 + lc]);
                unsigned b1 = __float_as_uint(Ks[(n + lr) * QP + k0 + lc + 4]);
                mma_tf32(s[nf], a0, a1, a2, a3, b0, b1);
            }
        }

#pragma unroll
        for (int nf = 0; nf < 4; nf++) {
            int col = n0s + nf * 8 + lc * 2;
            *(float2*)&Sh[(m0 + lr)     * SP + col] = make_float2(s[nf][0], s[nf][1]);
            *(float2*)&Sh[(m0 + lr + 8) * SP + col] = make_float2(s[nf][2], s[nf][3]);
        }
        __syncthreads();

        if (tid < 64) {
            int rr = tid;
            float* Sr = &Sh[rr * SP];
            float* Lr = &Sl[rr * SP];
            bool diag = (j == qt);
            float m = rowm[rr], mn = m;
#pragma unroll 8
            for (int c = 0; c < 64; c++) {
                float sv = (diag && c > rr) ? -3e30f : Sr[c];
                mn = fmaxf(mn, sv);
            }
            float a = __expf(m - mn);
            float l = rowl[rr] * a;
#pragma unroll 8
            for (int c = 0; c < 64; c++) {
                float sv = (diag && c > rr) ? -3e30f : Sr[c];
                float p = __expf(sv - mn);
                l += p;
                unsigned ph = f2tf32(p);
                float pl = p - __uint_as_float(ph);
                Sr[c] = __uint_as_float(ph);
                Lr[c] = __uint_as_float(f2tf32(pl));
            }
            rowm[rr] = mn; rowl[rr] = l; ralp[rr] = a;
        }
        __syncthreads();

        float aL = ralp[m0 + lr], aH = ralp[m0 + 8 + lr];
#pragma unroll
        for (int nf = 0; nf < 8; nf++) {
            o[nf][0] *= aL; o[nf][1] *= aL; o[nf][2] *= aH; o[nf][3] *= aH;
        }

#pragma unroll
        for (int ks = 0; ks < 8; ks++) {
            int k0 = ks * 8;
            unsigned h0 = __float_as_uint(Sh[(m0 + lr)     * SP + k0 + lc]);
            unsigned h1 = __float_as_uint(Sh[(m0 + lr + 8) * SP + k0 + lc]);
            unsigned h2 = __float_as_uint(Sh[(m0 + lr)     * SP + k0 + lc + 4]);
            unsigned h3 = __float_as_uint(Sh[(m0 + lr + 8) * SP + k0 + lc + 4]);
            unsigned l0 = __float_as_uint(Sl[(m0 + lr)     * SP + k0 + lc]);
            unsigned l1 = __float_as_uint(Sl[(m0 + lr + 8) * SP + k0 + lc]);
            unsigned l2 = __float_as_uint(Sl[(m0 + lr)     * SP + k0 + lc + 4]);
            unsigned l3 = __float_as_uint(Sl[(m0 + lr + 8) * SP + k0 + lc + 4]);
#pragma unroll
            for (int nf = 0; nf < 8; nf++) {
                int n = n0d + nf * 8;
                unsigned b0 = __float_as_uint(Vs[(k0 + lc)     * VP + n + lr]);
                unsigned b1 = __float_as_uint(Vs[(k0 + lc + 4) * VP + n + lr]);
                mma_tf32(o[nf], h0, h1, h2, h3, b0, b1);
                mma_tf32(o[nf], l0, l1, l2, l3, b0, b1);
            }
        }
        __syncthreads();
    }

    // epilogue: 1/l + sigmoid gate + split-bf16 output (feeds bf16x3 w_o GEMM)
#pragma unroll
    for (int half = 0; half < 2; half++) {
        int rr = m0 + half * 8 + lr;
        float linv = 1.0f / rowl[rr];
        int grow = qt * 64 + rr;
        const float* gbase = qg + (((size_t)(b * T_ + grow) * H_ + h) * 2 * HD_) + HD_;
        size_t off = ((size_t)(b * T_ + grow) * (H_ * HD_)) + h * HD_;
        __nv_bfloat16* hp = Oh + off;
        __nv_bfloat16* lp = Ol + off;
#pragma unroll
        for (int nf = 0; nf < 8; nf++) {
            int d = n0d + nf * 8 + lc * 2;
#pragma unroll
            for (int e = 0; e < 2; e++) {
                float gt = gbase[d + e];
                float sg = 1.0f / (1.0f + __expf(-gt));
                float val = o[nf][half * 2 + e] * linv * sg;
                __nv_bfloat16 hh, ll;
                split1(val, hh, ll);
                hp[d + e] = hh;
                lp[d + e] = ll;
            }
        }
    }
}

// ---------------- launch ----------------
extern "C" void kernel_launch(void* const* d_in, const int* in_sizes, int n_in,
                              void* d_out, int out_size) {
    const float* x    = (const float*)d_in[0];
    const float* w_q  = (const float*)d_in[1];
    const float* w_k  = (const float*)d_in[2];
    const float* w_v  = (const float*)d_in[3];
    const float* w_o  = (const float*)d_in[4];
    const float* qnw  = (const float*)d_in[5];
    const float* knw  = (const float*)d_in[6];
    const float* cs   = (const float*)d_in[7];
    const float* sn   = (const float*)d_in[8];
    float* out = (float*)d_out;

    float *qg, *q, *k, *v;
    __nv_bfloat16 *xh, *xl, *wqh, *wql, *wkh, *wkl, *wvh, *wvl, *woh, *wol, *ah, *al;
    cudaGetSymbolAddress((void**)&qg,  g_qg);
    cudaGetSymbolAddress((void**)&q,   g_q);
    cudaGetSymbolAddress((void**)&k,   g_k);
    cudaGetSymbolAddress((void**)&v,   g_v);
    cudaGetSymbolAddress((void**)&xh,  g_xh);
    cudaGetSymbolAddress((void**)&xl,  g_xl);
    cudaGetSymbolAddress((void**)&wqh, g_wqh);
    cudaGetSymbolAddress((void**)&wql, g_wql);
    cudaGetSymbolAddress((void**)&wkh, g_wkh);
    cudaGetSymbolAddress((void**)&wkl, g_wkl);
    cudaGetSymbolAddress((void**)&wvh, g_wvh);
    cudaGetSymbolAddress((void**)&wvl, g_wvl);
    cudaGetSymbolAddress((void**)&woh, g_woh);
    cudaGetSymbolAddress((void**)&wol, g_wol);
    cudaGetSymbolAddress((void**)&ah,  g_ah);
    cudaGetSymbolAddress((void**)&al,  g_al);

    cudaFuncSetAttribute((const void*)flash_tc,
                         cudaFuncAttributeMaxDynamicSharedMemorySize, FLASH_SMEM);
    cudaFuncSetAttribute((const void*)gemm_bf16,
                         cudaFuncAttributeMaxDynamicSharedMemorySize, GB_SMEM);

    const int M  = B_ * T_;       // 4096
    const int NQ = 2 * H_ * HD_;  // 4096
    const int NKV = G_ * HD_;     // 512

    // split conversions
    {
        int n4 = (B_ * T_ * D_) / 4;
        cvt_split<<<(n4 + 255) / 256, 256>>>(x, xh, xl, n4);
        cvt_split_t<<<dim3(NQ / 32, D_ / 32),  dim3(32, 8)>>>(w_q, wqh, wql, D_, NQ);
        cvt_split_t<<<dim3(NKV / 32, D_ / 32), dim3(32, 8)>>>(w_k, wkh, wkl, D_, NKV);
        cvt_split_t<<<dim3(NKV / 32, D_ / 32), dim3(32, 8)>>>(w_v, wvh, wvl, D_, NKV);
        cvt_split_t<<<dim3(D_ / 32, (H_ * HD_) / 32), dim3(32, 8)>>>(w_o, woh, wol, H_ * HD_, D_);
    }

    // QKV projections (bf16 3-pass HMMA)
    gemm_bf16<<<dim3(NQ / 128,  M / 128), 256, GB_SMEM>>>(xh, xl, wqh, wql, qg, M, NQ,  D_);
    gemm_bf16<<<dim3(NKV / 128, M / 128), 256, GB_SMEM>>>(xh, xl, wkh, wkl, k,  M, NKV, D_);
    gemm_bf16<<<dim3(NKV / 128, M / 128), 256, GB_SMEM>>>(xh, xl, wvh, wvl, v,  M, NKV, D_);

    // norms + rope (emit tf32 bits); V -> tf32 bits
    qnorm_rope<<<dim3(T_, B_ * H_), 128>>>(qg, q, qnw, cs, sn);
    knorm_rope<<<dim3(T_, B_ * G_), 128>>>(k, knw, cs, sn);
    {
        int n4 = (B_ * T_ * G_ * HD_) / 4;
        cvt_tf32<<<(n4 + 255) / 256, 256>>>(v, v, n4);
    }

    // attention + gate (tf32 tensor cores; epilogue emits split-bf16 attn)
    flash_tc<<<dim3(T_ / 64, B_ * H_), 256, FLASH_SMEM>>>(q, k, v, qg, ah, al);

    // output projection (bf16 3-pass HMMA)
    gemm_bf16<<<dim3(D_ / 128, M / 128), 256, GB_SMEM>>>(ah, al, woh, wol, out, M, D_, H_ * HD_);
}

// round 14
// speedup vs baseline: 1.5760x; 1.5760x over previous
#include <cuda_runtime.h>
#include <cuda_bf16.h>
#include <math.h>
#include <stdint.h>

#define B_  2
#define T_  2048
#define D_  2048
#define H_  16
#define G_  4
#define HD_ 128

// ---------------- scratch (static device globals; no allocation) ----------------
__device__ float g_qg[(size_t)B_ * T_ * H_ * 2 * HD_];
__device__ float g_q [(size_t)B_ * H_ * T_ * HD_];
__device__ float g_k [(size_t)B_ * T_ * G_ * HD_];
__device__ float g_v [(size_t)B_ * T_ * G_ * HD_];
__device__ float g_attn[(size_t)B_ * T_ * H_ * HD_];
__device__ float g_xt [(size_t)B_ * T_ * D_];
__device__ float g_wqt[(size_t)D_ * 2 * H_ * HD_];
__device__ float g_wkt[(size_t)D_ * G_ * HD_];
__device__ float g_wvt[(size_t)D_ * G_ * HD_];
__device__ float g_wot[(size_t)H_ * HD_ * D_];

// ---------------- tf32 helpers ----------------
__device__ __forceinline__ unsigned f2tf32(float x) {
    unsigned r;
    asm("cvt.rna.tf32.f32 %0, %1;" : "=r"(r) : "f"(x));
    return r;
}

__device__ __forceinline__ void mma_tf32(float* c, unsigned a0, unsigned a1, unsigned a2,
                                         unsigned a3, unsigned b0, unsigned b1) {
    asm volatile(
        "mma.sync.aligned.m16n8k8.row.col.f32.tf32.tf32.f32 "
        "{%0,%1,%2,%3}, {%4,%5,%6,%7}, {%8,%9}, {%0,%1,%2,%3};\n"
        : "+f"(c[0]), "+f"(c[1]), "+f"(c[2]), "+f"(c[3])
        : "r"(a0), "r"(a1), "r"(a2), "r"(a3), "r"(b0), "r"(b1));
}

__global__ void cvt_tf32(const float* __restrict__ in, float* __restrict__ out, int n4) {
    int i = blockIdx.x * blockDim.x + threadIdx.x;
    if (i < n4) {
        float4 v = ((const float4*)in)[i];
        uint4 o;
        o.x = f2tf32(v.x); o.y = f2tf32(v.y); o.z = f2tf32(v.z); o.w = f2tf32(v.w);
        ((uint4*)out)[i] = o;
    }
}

// ---------------- tf32 GEMM, 128x128 tile, BK=32, double-buffered ----------------
#define AP2 36     // words per A row (32 + 4 pad): 4r+kc covers 32 banks
#define BP2 136    // words per B row: kc*8+r covers 32 banks
#define BUF_W (128 * AP2 + 32 * BP2)            // 8960 words per buffer
#define GEMM_SMEM (2 * BUF_W * 4)               // 71680 bytes

__device__ __forceinline__ void cp16(float* smem_dst, const float* gsrc) {
    unsigned sa = (unsigned)__cvta_generic_to_shared(smem_dst);
    asm volatile("cp.async.cg.shared.global [%0], [%1], 16;\n" :: "r"(sa), "l"(gsrc));
}

__global__ __launch_bounds__(256, 2) void gemm_tf32(
        const float* __restrict__ A, const float* __restrict__ Bm,
        float* __restrict__ C, int M, int N, int K) {
    extern __shared__ float dsm[];

    int tid  = threadIdx.x;
    int lane = tid & 31;
    int warp = tid >> 5;
    int wm = (warp & 1) * 64;
    int wn = (warp >> 1) * 32;
    int bx = blockIdx.x, by = blockIdx.y;

    const float* Ab = A + (size_t)by * 128 * K;
    const float* Bb = Bm + (size_t)bx * 128;

    // A: 1024 16B-chunks: row=id>>3 (0..127), c=id&7 ; B: 1024 chunks: row=id>>5 (0..31), nc=id&31
    float acc[4][4][4];
#pragma unroll
    for (int i = 0; i < 4; i++)
#pragma unroll
        for (int j = 0; j < 4; j++)
#pragma unroll
            for (int c = 0; c < 4; c++) acc[i][j][c] = 0.f;

    int nk = K / 32;

    // prologue: stage 0 into buffer 0
    {
        float* Asb = dsm;
        float* Bsb = dsm + 128 * AP2;
#pragma unroll
        for (int j = 0; j < 4; j++) {
            int id = tid + 256 * j;
            int ar = id >> 3, ac = id & 7;
            cp16(&Asb[ar * AP2 + ac * 4], Ab + (size_t)ar * K + ac * 4);
            int br = id >> 5, bn = id & 31;
            cp16(&Bsb[br * BP2 + bn * 4], Bb + (size_t)br * N + bn * 4);
        }
        asm volatile("cp.async.commit_group;\n");
    }

    int buf = 0;
    for (int kt = 0; kt < nk; kt++) {
        asm volatile("cp.async.wait_group 0;\n");
        __syncthreads();

        if (kt + 1 < nk) {
            int kb = (kt + 1) * 32;
            float* Asb = dsm + (buf ^ 1) * BUF_W;
            float* Bsb = Asb + 128 * AP2;
#pragma unroll
            for (int j = 0; j < 4; j++) {
                int id = tid + 256 * j;
                int ar = id >> 3, ac = id & 7;
                cp16(&Asb[ar * AP2 + ac * 4], Ab + (size_t)ar * K + kb + ac * 4);
                int br = id >> 5, bn = id & 31;
                cp16(&Bsb[br * BP2 + bn * 4], Bb + (size_t)(kb + br) * N + bn * 4);
            }
        }
        asm volatile("cp.async.commit_group;\n");

        const float* Asb = dsm + buf * BUF_W;
        const float* Bsb = Asb + 128 * AP2;
        int r  = lane >> 2;
        int kc = lane & 3;
#pragma unroll
        for (int ks = 0; ks < 4; ks++) {
            int k0 = ks * 8;
            unsigned af[4][4];
#pragma unroll
            for (int mf = 0; mf < 4; mf++) {
                int m = wm + mf * 16;
                af[mf][0] = __float_as_uint(Asb[(m + r)     * AP2 + k0 + kc]);
                af[mf][1] = __float_as_uint(Asb[(m + r + 8) * AP2 + k0 + kc]);
                af[mf][2] = __float_as_uint(Asb[(m + r)     * AP2 + k0 + kc + 4]);
                af[mf][3] = __float_as_uint(Asb[(m + r + 8) * AP2 + k0 + kc + 4]);
            }
            unsigned bf[4][2];
#pragma unroll
            for (int nf = 0; nf < 4; nf++) {
                int n = wn + nf * 8;
                bf[nf][0] = __float_as_uint(Bsb[(k0 + kc)     * BP2 + n + r]);
                bf[nf][1] = __float_as_uint(Bsb[(k0 + kc + 4) * BP2 + n + r]);
            }
#pragma unroll
            for (int mf = 0; mf < 4; mf++)
#pragma unroll
                for (int nf = 0; nf < 4; nf++)
                    mma_tf32(acc[mf][nf], af[mf][0], af[mf][1], af[mf][2], af[mf][3],
                             bf[nf][0], bf[nf][1]);
        }
        buf ^= 1;
    }

    int r  = lane >> 2;
    int cc = (lane & 3) * 2;
#pragma unroll
    for (int mf = 0; mf < 4; mf++) {
#pragma unroll
        for (int nf = 0; nf < 4; nf++) {
            size_t row0 = (size_t)(by * 128 + wm + mf * 16 + r);
            int col = bx * 128 + wn + nf * 8 + cc;
            *(float2*)&C[row0 * N + col]       = make_float2(acc[mf][nf][0], acc[mf][nf][1]);
            *(float2*)&C[(row0 + 8) * N + col] = make_float2(acc[mf][nf][2], acc[mf][nf][3]);
        }
    }
}

// ---------------- Q: RMSNorm + RoPE + scale -> tf32 bits ----------------
__global__ void qnorm_rope(const float* __restrict__ qg, float* __restrict__ qout,
                           const float* __restrict__ w, const float* __restrict__ cs,
                           const float* __restrict__ sn) {
    int t = blockIdx.x;
    int bh = blockIdx.y;
    int b = bh >> 4, h = bh & 15;
    int i = threadIdx.x;  // 128

    const float* row = qg + (((size_t)(b * T_ + t) * H_ + h) * 2 * HD_);
    float v = row[i];

    float ss = v * v;
#pragma unroll
    for (int o = 16; o > 0; o >>= 1) ss += __shfl_xor_sync(0xffffffffu, ss, o);
    __shared__ float warpsum[4];
    __shared__ float normed[HD_];
    if ((i & 31) == 0) warpsum[i >> 5] = ss;
    __syncthreads();
    float tot = warpsum[0] + warpsum[1] + warpsum[2] + warpsum[3];
    float rms = rsqrtf(tot * (1.0f / HD_) + 1e-6f);
    float xv = v * rms * w[i];
    normed[i] = xv;
    __syncthreads();
    float rot = (i < 64) ? -normed[i + 64] : normed[i - 64];
    float o = (xv * cs[t * HD_ + i] + rot * sn[t * HD_ + i]) * 0.08838834764831845f;
    ((unsigned*)qout)[(((size_t)(b * H_ + h) * T_) + t) * HD_ + i] = f2tf32(o);
}

// ---------------- K: RMSNorm + RoPE -> tf32 bits (in place) ----------------
__global__ void knorm_rope(float* __restrict__ kbuf, const float* __restrict__ w,
                           const float* __restrict__ cs, const float* __restrict__ sn) {
    int t = blockIdx.x;
    int bg = blockIdx.y;
    int b = bg >> 2, g = bg & 3;
    int i = threadIdx.x;

    size_t base = ((size_t)(b * T_ + t) * G_ + g) * HD_;
    float v = kbuf[base + i];

    float ss = v * v;
#pragma unroll
    for (int o = 16; o > 0; o >>= 1) ss += __shfl_xor_sync(0xffffffffu, ss, o);
    __shared__ float warpsum[4];
    __shared__ float normed[HD_];
    if ((i & 31) == 0) warpsum[i >> 5] = ss;
    __syncthreads();
    float tot = warpsum[0] + warpsum[1] + warpsum[2] + warpsum[3];
    float rms = rsqrtf(tot * (1.0f / HD_) + 1e-6f);
    float xv = v * rms * w[i];
    normed[i] = xv;
    __syncthreads();
    float rot = (i < 64) ? -normed[i + 64] : normed[i - 64];
    ((unsigned*)kbuf)[base + i] = f2tf32(xv * cs[t * HD_ + i] + rot * sn[t * HD_ + i]);
}

// ---------------- causal GQA flash attention on tf32 tensor cores ----------------
#define QP 132
#define VP 136
#define SP 68
#define FLASH_SMEM ((64 * QP * 2 + 64 * VP + 64 * SP * 2 + 3 * 64) * 4)

__global__ __launch_bounds__(256, 1) void flash_tc(
        const float* __restrict__ Q, const float* __restrict__ K,
        const float* __restrict__ V, const float* __restrict__ qg,
        float* __restrict__ Oout) {
    extern __shared__ float sm[];
    float* Qs   = sm;
    float* Ks   = Qs + 64 * QP;
    float* Vs   = Ks + 64 * QP;
    float* Sh   = Vs + 64 * VP;
    float* Sl   = Sh + 64 * SP;
    float* rowm = Sl + 64 * SP;
    float* rowl = rowm + 64;
    float* ralp = rowl + 64;

    int qt = gridDim.x - 1 - blockIdx.x;
    int bh = blockIdx.y;
    int b = bh >> 4, h = bh & 15;
    int g = h >> 2;
    int tid = threadIdx.x;
    int w = tid >> 5, lane = tid & 31;
    int m0  = (w & 3) * 16;
    int n0s = (w >> 2) * 32;
    int n0d = (w >> 2) * 64;
    int lr = lane >> 2, lc = lane & 3;

    const float* Qb = Q + (((size_t)(b * H_ + h) * T_) + qt * 64) * HD_;
    const float* Kb = K + ((size_t)b * T_ * G_ + g) * HD_;
    const float* Vb = V + ((size_t)b * T_ * G_ + g) * HD_;

    for (int i = tid; i < 64 * 32; i += 256) {
        int r = i >> 5, c4 = (i & 31) * 4;
        *(float4*)&Qs[r * QP + c4] = *(const float4*)(Qb + r * HD_ + c4);
    }
    if (tid < 64) { rowm[tid] = -3e30f; rowl[tid] = 0.f; }

    float o[8][4];
#pragma unroll
    for (int nf = 0; nf < 8; nf++)
#pragma unroll
        for (int c = 0; c < 4; c++) o[nf][c] = 0.f;
    __syncthreads();

    for (int j = 0; j <= qt; j++) {
        const float* Kt = Kb + (size_t)(j * 64) * (G_ * HD_);
        const float* Vt = Vb + (size_t)(j * 64) * (G_ * HD_);
        for (int i = tid; i < 64 * 32; i += 256) {
            int r = i >> 5, c4 = (i & 31) * 4;
            *(float4*)&Ks[r * QP + c4] = *(const float4*)(Kt + (size_t)r * (G_ * HD_) + c4);
            *(float4*)&Vs[r * VP + c4] = *(const float4*)(Vt + (size_t)r * (G_ * HD_) + c4);
        }
        __syncthreads();

        // ---- S = Q K^T ----
        float s[4][4];
#pragma unroll
        for (int nf = 0; nf < 4; nf++)
#pragma unroll
            for (int c = 0; c < 4; c++) s[nf][c] = 0.f;

#pragma unroll
        for (int ks = 0; ks < 16; ks++) {
            int k0 = ks * 8;
            unsigned a0 = __float_as_uint(Qs[(m0 + lr)     * QP + k0 + lc]);
            unsigned a1 = __float_as_uint(Qs[(m0 + lr + 8) * QP + k0 + lc]);
            unsigned a2 = __float_as_uint(Qs[(m0 + lr)     * QP + k0 + lc + 4]);
            unsigned a3 = __float_as_uint(Qs[(m0 + lr + 8) * QP + k0 + lc + 4]);
#pragma unroll
            for (int nf = 0; nf < 4; nf++) {
                int n = n0s + nf * 8;
                unsigned b0 = __float_as_uint(Ks[(n + lr) * QP + k0 + lc]);
                unsigned b1 = __float_as_uint(Ks[(n + lr) * QP + k0 + lc + 4]);
                mma_tf32(s[nf], a0, a1, a2, a3, b0, b1);
            }
        }

#pragma unroll
        for (int nf = 0; nf < 4; nf++) {
            int col = n0s + nf * 8 + lc * 2;
            *(float2*)&Sh[(m0 + lr)     * SP + col] = make_float2(s[nf][0], s[nf][1]);
            *(float2*)&Sh[(m0 + lr + 8) * SP + col] = make_float2(s[nf][2], s[nf][3]);
        }
        __syncthreads();

        // ---- parallel softmax: 4 threads/row x 16 cols, shfl-reduce within 4-lane group ----
        {
            int rr  = tid >> 2;      // 0..63
            int seg = tid & 3;       // column segment
            float* Sr = &Sh[rr * SP];
            float* Lr = &Sl[rr * SP];
            bool diag = (j == qt);
            float sv[16];
            float mloc = -3e30f;
#pragma unroll
            for (int c = 0; c < 16; c++) {
                int col = seg * 16 + c;
                float v = (diag && col > rr) ? -3e30f : Sr[col];
                sv[c] = v;
                mloc = fmaxf(mloc, v);
            }
            mloc = fmaxf(mloc, __shfl_xor_sync(0xffffffffu, mloc, 1));
            mloc = fmaxf(mloc, __shfl_xor_sync(0xffffffffu, mloc, 2));
            float mold = rowm[rr];
            float mn = fmaxf(mold, mloc);
            float lloc = 0.f;
#pragma unroll
            for (int c = 0; c < 16; c++) {
                int col = seg * 16 + c;
                float p = __expf(sv[c] - mn);
                lloc += p;
                unsigned ph = f2tf32(p);
                Sr[col] = __uint_as_float(ph);
                Lr[col] = __uint_as_float(f2tf32(p - __uint_as_float(ph)));
            }
            lloc += __shfl_xor_sync(0xffffffffu, lloc, 1);
            lloc += __shfl_xor_sync(0xffffffffu, lloc, 2);
            if (seg == 0) {
                float a = __expf(mold - mn);
                rowl[rr] = rowl[rr] * a + lloc;
                rowm[rr] = mn;
                ralp[rr] = a;
            }
        }
        __syncthreads();

        float aL = ralp[m0 + lr], aH = ralp[m0 + 8 + lr];
#pragma unroll
        for (int nf = 0; nf < 8; nf++) {
            o[nf][0] *= aL; o[nf][1] *= aL; o[nf][2] *= aH; o[nf][3] *= aH;
        }

        // ---- O += P V (2-pass: P hi + P lo) ----
#pragma unroll
        for (int ks = 0; ks < 8; ks++) {
            int k0 = ks * 8;
            unsigned h0 = __float_as_uint(Sh[(m0 + lr)     * SP + k0 + lc]);
            unsigned h1 = __float_as_uint(Sh[(m0 + lr + 8) * SP + k0 + lc]);
            unsigned h2 = __float_as_uint(Sh[(m0 + lr)     * SP + k0 + lc + 4]);
            unsigned h3 = __float_as_uint(Sh[(m0 + lr + 8) * SP + k0 + lc + 4]);
            unsigned l0 = __float_as_uint(Sl[(m0 + lr)     * SP + k0 + lc]);
            unsigned l1 = __float_as_uint(Sl[(m0 + lr + 8) * SP + k0 + lc]);
            unsigned l2 = __float_as_uint(Sl[(m0 + lr)     * SP + k0 + lc + 4]);
            unsigned l3 = __float_as_uint(Sl[(m0 + lr + 8) * SP + k0 + lc + 4]);
#pragma unroll
            for (int nf = 0; nf < 8; nf++) {
                int n = n0d + nf * 8;
                unsigned b0 = __float_as_uint(Vs[(k0 + lc)     * VP + n + lr]);
                unsigned b1 = __float_as_uint(Vs[(k0 + lc + 4) * VP + n + lr]);
                mma_tf32(o[nf], h0, h1, h2, h3, b0, b1);
                mma_tf32(o[nf], l0, l1, l2, l3, b0, b1);
            }
        }
        __syncthreads();
    }

    // ---- epilogue: 1/l, sigmoid gate, tf32 rounding ----
#pragma unroll
    for (int half = 0; half < 2; half++) {
        int rr = m0 + half * 8 + lr;
        float linv = 1.0f / rowl[rr];
        int grow = qt * 64 + rr;
        const float* gbase = qg + (((size_t)(b * T_ + grow) * H_ + h) * 2 * HD_) + HD_;
        unsigned* obase = (unsigned*)(Oout + ((size_t)(b * T_ + grow) * (H_ * HD_)) + h * HD_);
#pragma unroll
        for (int nf = 0; nf < 8; nf++) {
            int d = n0d + nf * 8 + lc * 2;
#pragma unroll
            for (int e = 0; e < 2; e++) {
                float gt = gbase[d + e];
                float sg = 1.0f / (1.0f + __expf(-gt));
                float val = o[nf][half * 2 + e] * linv * sg;
                obase[d + e] = f2tf32(val);
            }
        }
    }
}

// ---------------- launch ----------------
extern "C" void kernel_launch(void* const* d_in, const int* in_sizes, int n_in,
                              void* d_out, int out_size) {
    const float* x    = (const float*)d_in[0];
    const float* w_q  = (const float*)d_in[1];
    const float* w_k  = (const float*)d_in[2];
    const float* w_v  = (const float*)d_in[3];
    const float* w_o  = (const float*)d_in[4];
    const float* qnw  = (const float*)d_in[5];
    const float* knw  = (const float*)d_in[6];
    const float* cs   = (const float*)d_in[7];
    const float* sn   = (const float*)d_in[8];
    float* out = (float*)d_out;

    float *qg, *q, *k, *v, *attn, *xt, *wqt, *wkt, *wvt, *wot;
    cudaGetSymbolAddress((void**)&qg,   g_qg);
    cudaGetSymbolAddress((void**)&q,    g_q);
    cudaGetSymbolAddress((void**)&k,    g_k);
    cudaGetSymbolAddress((void**)&v,    g_v);
    cudaGetSymbolAddress((void**)&attn, g_attn);
    cudaGetSymbolAddress((void**)&xt,   g_xt);
    cudaGetSymbolAddress((void**)&wqt,  g_wqt);
    cudaGetSymbolAddress((void**)&wkt,  g_wkt);
    cudaGetSymbolAddress((void**)&wvt,  g_wvt);
    cudaGetSymbolAddress((void**)&wot,  g_wot);

    cudaFuncSetAttribute((const void*)flash_tc,
                         cudaFuncAttributeMaxDynamicSharedMemorySize, FLASH_SMEM);
    cudaFuncSetAttribute((const void*)gemm_tf32,
                         cudaFuncAttributeMaxDynamicSharedMemorySize, GEMM_SMEM);

    const int M = B_ * T_;  // 4096

    // tf32 rounding pre-pass
    {
        int n4;
        n4 = (B_ * T_ * D_) / 4;          cvt_tf32<<<(n4 + 255) / 256, 256>>>(x,   xt,  n4);
        n4 = (D_ * 2 * H_ * HD_) / 4;     cvt_tf32<<<(n4 + 255) / 256, 256>>>(w_q, wqt, n4);
        n4 = (D_ * G_ * HD_) / 4;         cvt_tf32<<<(n4 + 255) / 256, 256>>>(w_k, wkt, n4);
        n4 = (D_ * G_ * HD_) / 4;         cvt_tf32<<<(n4 + 255) / 256, 256>>>(w_v, wvt, n4);
        n4 = (H_ * HD_ * D_) / 4;         cvt_tf32<<<(n4 + 255) / 256, 256>>>(w_o, wot, n4);
    }

    // QKV projections (tensor cores, tf32, BK=32)
    gemm_tf32<<<dim3((2 * H_ * HD_) / 128, M / 128), 256, GEMM_SMEM>>>(xt, wqt, qg, M, 2 * H_ * HD_, D_);
    gemm_tf32<<<dim3((G_ * HD_) / 128,     M / 128), 256, GEMM_SMEM>>>(xt, wkt, k,  M, G_ * HD_,     D_);
    gemm_tf32<<<dim3((G_ * HD_) / 128,     M / 128), 256, GEMM_SMEM>>>(xt, wvt, v,  M, G_ * HD_,     D_);

    // norms + rope (emit tf32 bits); V -> tf32 bits
    qnorm_rope<<<dim3(T_, B_ * H_), 128>>>(qg, q, qnw, cs, sn);
    knorm_rope<<<dim3(T_, B_ * G_), 128>>>(k, knw, cs, sn);
    {
        int n4 = (B_ * T_ * G_ * HD_) / 4;
        cvt_tf32<<<(n4 + 255) / 256, 256>>>(v, v, n4);
    }

    // attention + gate (tf32 tensor cores)
    flash_tc<<<dim3(T_ / 64, B_ * H_), 256, FLASH_SMEM>>>(q, k, v, qg, attn);

    // output projection (tensor cores, tf32, BK=32)
    gemm_tf32<<<dim3(D_ / 128, M / 128), 256, GEMM_SMEM>>>(attn, wot, out, M, D_, D_);
}

// round 15
// speedup vs baseline: 1.6897x; 1.0721x over previous
#include <cuda_runtime.h>
#include <cuda_bf16.h>
#include <math.h>
#include <stdint.h>

#define B_  2
#define T_  2048
#define D_  2048
#define H_  16
#define G_  4
#define HD_ 128
#define QKVN 5120                  // fused projection width: 4096 q+gate | 512 k | 512 v
#define KOFF 4096
#define VOFF 4608

// ---------------- scratch (static device globals; no allocation) ----------------
__device__ float g_qkv[(size_t)B_ * T_ * QKVN];          // fused q+gate | k | v
__device__ float g_q  [(size_t)B_ * H_ * T_ * HD_];      // tf32 bits (B,H,T,HD)
__device__ float g_attn[(size_t)B_ * T_ * H_ * HD_];     // tf32 bits
__device__ float g_xt  [(size_t)B_ * T_ * D_];           // tf32 bits
__device__ float g_wqkvt[(size_t)D_ * QKVN];             // tf32 bits, fused weights
__device__ float g_wot [(size_t)H_ * HD_ * D_];          // tf32 bits

// ---------------- tf32 helpers ----------------
__device__ __forceinline__ unsigned f2tf32(float x) {
    unsigned r;
    asm("cvt.rna.tf32.f32 %0, %1;" : "=r"(r) : "f"(x));
    return r;
}

__device__ __forceinline__ void mma_tf32(float* c, unsigned a0, unsigned a1, unsigned a2,
                                         unsigned a3, unsigned b0, unsigned b1) {
    asm volatile(
        "mma.sync.aligned.m16n8k8.row.col.f32.tf32.tf32.f32 "
        "{%0,%1,%2,%3}, {%4,%5,%6,%7}, {%8,%9}, {%0,%1,%2,%3};\n"
        : "+f"(c[0]), "+f"(c[1]), "+f"(c[2]), "+f"(c[3])
        : "r"(a0), "r"(a1), "r"(a2), "r"(a3), "r"(b0), "r"(b1));
}

__global__ void cvt_tf32(const float* __restrict__ in, float* __restrict__ out, int n4) {
    int i = blockIdx.x * blockDim.x + threadIdx.x;
    if (i < n4) {
        float4 v = ((const float4*)in)[i];
        uint4 o;
        o.x = f2tf32(v.x); o.y = f2tf32(v.y); o.z = f2tf32(v.z); o.w = f2tf32(v.w);
        ((uint4*)out)[i] = o;
    }
}

// strided cvt: W[K,N] (contiguous) -> out[k*Ntot + col0 + n], tf32-rounded
__global__ void cvt_tf32_s(const float* __restrict__ in, float* __restrict__ out,
                           int N4, int Ntot, int col0, int n4) {
    int i = blockIdx.x * blockDim.x + threadIdx.x;
    if (i < n4) {
        int kk = i / N4, nc = i - kk * N4;
        float4 v = ((const float4*)in)[i];
        uint4 o;
        o.x = f2tf32(v.x); o.y = f2tf32(v.y); o.z = f2tf32(v.z); o.w = f2tf32(v.w);
        *(uint4*)(out + (size_t)kk * Ntot + col0 + nc * 4) = o;
    }
}

// in-place tf32 rounding of the V region inside g_qkv
__global__ void cvt_v_region(float* __restrict__ qkv, int n4) {
    int i = blockIdx.x * blockDim.x + threadIdx.x;
    if (i < n4) {
        int row = i >> 7, c4 = (i & 127) * 4;     // 128 vec4 per 512-col row
        float* p = qkv + (size_t)row * QKVN + VOFF + c4;
        float4 v = *(float4*)p;
        uint4 o;
        o.x = f2tf32(v.x); o.y = f2tf32(v.y); o.z = f2tf32(v.z); o.w = f2tf32(v.w);
        *(uint4*)p = o;
    }
}

// ---------------- tf32 GEMM, 128x128 tile, BK=32, double-buffered (R14-proven) ----------------
#define AP2 36
#define BP2 136
#define BUF_W (128 * AP2 + 32 * BP2)
#define GEMM_SMEM (2 * BUF_W * 4)

__device__ __forceinline__ void cp16(float* smem_dst, const float* gsrc) {
    unsigned sa = (unsigned)__cvta_generic_to_shared(smem_dst);
    asm volatile("cp.async.cg.shared.global [%0], [%1], 16;\n" :: "r"(sa), "l"(gsrc));
}

__global__ __launch_bounds__(256, 2) void gemm_tf32(
        const float* __restrict__ A, const float* __restrict__ Bm,
        float* __restrict__ C, int M, int N, int K) {
    extern __shared__ float dsm[];

    int tid  = threadIdx.x;
    int lane = tid & 31;
    int warp = tid >> 5;
    int wm = (warp & 1) * 64;
    int wn = (warp >> 1) * 32;
    int bx = blockIdx.x, by = blockIdx.y;

    const float* Ab = A + (size_t)by * 128 * K;
    const float* Bb = Bm + (size_t)bx * 128;

    float acc[4][4][4];
#pragma unroll
    for (int i = 0; i < 4; i++)
#pragma unroll
        for (int j = 0; j < 4; j++)
#pragma unroll
            for (int c = 0; c < 4; c++) acc[i][j][c] = 0.f;

    int nk = K / 32;

    {
        float* Asb = dsm;
        float* Bsb = dsm + 128 * AP2;
#pragma unroll
        for (int j = 0; j < 4; j++) {
            int id = tid + 256 * j;
            int ar = id >> 3, ac = id & 7;
            cp16(&Asb[ar * AP2 + ac * 4], Ab + (size_t)ar * K + ac * 4);
            int br = id >> 5, bn = id & 31;
            cp16(&Bsb[br * BP2 + bn * 4], Bb + (size_t)br * N + bn * 4);
        }
        asm volatile("cp.async.commit_group;\n");
    }

    int buf = 0;
    for (int kt = 0; kt < nk; kt++) {
        asm volatile("cp.async.wait_group 0;\n");
        __syncthreads();

        if (kt + 1 < nk) {
            int kb = (kt + 1) * 32;
            float* Asb = dsm + (buf ^ 1) * BUF_W;
            float* Bsb = Asb + 128 * AP2;
#pragma unroll
            for (int j = 0; j < 4; j++) {
                int id = tid + 256 * j;
                int ar = id >> 3, ac = id & 7;
                cp16(&Asb[ar * AP2 + ac * 4], Ab + (size_t)ar * K + kb + ac * 4);
                int br = id >> 5, bn = id & 31;
                cp16(&Bsb[br * BP2 + bn * 4], Bb + (size_t)(kb + br) * N + bn * 4);
            }
        }
        asm volatile("cp.async.commit_group;\n");

        const float* Asb = dsm + buf * BUF_W;
        const float* Bsb = Asb + 128 * AP2;
        int r  = lane >> 2;
        int kc = lane & 3;
#pragma unroll
        for (int ks = 0; ks < 4; ks++) {
            int k0 = ks * 8;
            unsigned af[4][4];
#pragma unroll
            for (int mf = 0; mf < 4; mf++) {
                int m = wm + mf * 16;
                af[mf][0] = __float_as_uint(Asb[(m + r)     * AP2 + k0 + kc]);
                af[mf][1] = __float_as_uint(Asb[(m + r + 8) * AP2 + k0 + kc]);
                af[mf][2] = __float_as_uint(Asb[(m + r)     * AP2 + k0 + kc + 4]);
                af[mf][3] = __float_as_uint(Asb[(m + r + 8) * AP2 + k0 + kc + 4]);
            }
            unsigned bf[4][2];
#pragma unroll
            for (int nf = 0; nf < 4; nf++) {
                int n = wn + nf * 8;
                bf[nf][0] = __float_as_uint(Bsb[(k0 + kc)     * BP2 + n + r]);
                bf[nf][1] = __float_as_uint(Bsb[(k0 + kc + 4) * BP2 + n + r]);
            }
#pragma unroll
            for (int mf = 0; mf < 4; mf++)
#pragma unroll
                for (int nf = 0; nf < 4; nf++)
                    mma_tf32(acc[mf][nf], af[mf][0], af[mf][1], af[mf][2], af[mf][3],
                             bf[nf][0], bf[nf][1]);
        }
        buf ^= 1;
    }

    int r  = lane >> 2;
    int cc = (lane & 3) * 2;
#pragma unroll
    for (int mf = 0; mf < 4; mf++) {
#pragma unroll
        for (int nf = 0; nf < 4; nf++) {
            size_t row0 = (size_t)(by * 128 + wm + mf * 16 + r);
            int col = bx * 128 + wn + nf * 8 + cc;
            *(float2*)&C[row0 * N + col]       = make_float2(acc[mf][nf][0], acc[mf][nf][1]);
            *(float2*)&C[(row0 + 8) * N + col] = make_float2(acc[mf][nf][2], acc[mf][nf][3]);
        }
    }
}

// ---------------- Q: RMSNorm + RoPE + scale -> tf32 bits (B,H,T,HD) ----------------
__global__ void qnorm_rope(const float* __restrict__ qkv, float* __restrict__ qout,
                           const float* __restrict__ w, const float* __restrict__ cs,
                           const float* __restrict__ sn) {
    int t = blockIdx.x;
    int bh = blockIdx.y;
    int b = bh >> 4, h = bh & 15;
    int i = threadIdx.x;  // 128

    const float* row = qkv + ((size_t)(b * T_ + t)) * QKVN + h * 2 * HD_;
    float v = row[i];

    float ss = v * v;
#pragma unroll
    for (int o = 16; o > 0; o >>= 1) ss += __shfl_xor_sync(0xffffffffu, ss, o);
    __shared__ float warpsum[4];
    __shared__ float normed[HD_];
    if ((i & 31) == 0) warpsum[i >> 5] = ss;
    __syncthreads();
    float tot = warpsum[0] + warpsum[1] + warpsum[2] + warpsum[3];
    float rms = rsqrtf(tot * (1.0f / HD_) + 1e-6f);
    float xv = v * rms * w[i];
    normed[i] = xv;
    __syncthreads();
    float rot = (i < 64) ? -normed[i + 64] : normed[i - 64];
    float o = (xv * cs[t * HD_ + i] + rot * sn[t * HD_ + i]) * 0.08838834764831845f;
    ((unsigned*)qout)[(((size_t)(b * H_ + h) * T_) + t) * HD_ + i] = f2tf32(o);
}

// ---------------- K: RMSNorm + RoPE -> tf32 bits, in place in g_qkv ----------------
__global__ void knorm_rope(float* __restrict__ qkv, const float* __restrict__ w,
                           const float* __restrict__ cs, const float* __restrict__ sn) {
    int t = blockIdx.x;
    int bg = blockIdx.y;
    int b = bg >> 2, g = bg & 3;
    int i = threadIdx.x;

    size_t base = ((size_t)(b * T_ + t)) * QKVN + KOFF + g * HD_;
    float v = qkv[base + i];

    float ss = v * v;
#pragma unroll
    for (int o = 16; o > 0; o >>= 1) ss += __shfl_xor_sync(0xffffffffu, ss, o);
    __shared__ float warpsum[4];
    __shared__ float normed[HD_];
    if ((i & 31) == 0) warpsum[i >> 5] = ss;
    __syncthreads();
    float tot = warpsum[0] + warpsum[1] + warpsum[2] + warpsum[3];
    float rms = rsqrtf(tot * (1.0f / HD_) + 1e-6f);
    float xv = v * rms * w[i];
    normed[i] = xv;
    __syncthreads();
    float rot = (i < 64) ? -normed[i + 64] : normed[i - 64];
    ((unsigned*)qkv)[base + i] = f2tf32(xv * cs[t * HD_ + i] + rot * sn[t * HD_ + i]);
}

// ---------------- causal GQA flash attention (tf32 MMA, single-pass PV) ----------------
#define QP 132
#define VP 136
#define SP 68
#define FLASH_SMEM ((64 * QP * 2 + 64 * VP + 64 * SP + 3 * 64) * 4)

__global__ __launch_bounds__(256, 1) void flash_tc(
        const float* __restrict__ Q, const float* __restrict__ qkv,
        float* __restrict__ Oout) {
    extern __shared__ float sm[];
    float* Qs   = sm;
    float* Ks   = Qs + 64 * QP;
    float* Vs   = Ks + 64 * QP;
    float* Sh   = Vs + 64 * VP;
    float* rowm = Sh + 64 * SP;
    float* rowl = rowm + 64;
    float* ralp = rowl + 64;

    int qt = gridDim.x - 1 - blockIdx.x;
    int bh = blockIdx.y;
    int b = bh >> 4, h = bh & 15;
    int g = h >> 2;
    int tid = threadIdx.x;
    int w = tid >> 5, lane = tid & 31;
    int m0  = (w & 3) * 16;
    int n0s = (w >> 2) * 32;
    int n0d = (w >> 2) * 64;
    int lr = lane >> 2, lc = lane & 3;

    const float* Qb = Q + (((size_t)(b * H_ + h) * T_) + qt * 64) * HD_;
    const float* Kb = qkv + (size_t)b * T_ * QKVN + KOFF + g * HD_;
    const float* Vb = qkv + (size_t)b * T_ * QKVN + VOFF + g * HD_;

    for (int i = tid; i < 64 * 32; i += 256) {
        int r = i >> 5, c4 = (i & 31) * 4;
        *(float4*)&Qs[r * QP + c4] = *(const float4*)(Qb + r * HD_ + c4);
    }
    if (tid < 64) { rowm[tid] = -3e30f; rowl[tid] = 0.f; }

    float o[8][4];
#pragma unroll
    for (int nf = 0; nf < 8; nf++)
#pragma unroll
        for (int c = 0; c < 4; c++) o[nf][c] = 0.f;
    __syncthreads();

    for (int j = 0; j <= qt; j++) {
        const float* Kt = Kb + (size_t)(j * 64) * QKVN;
        const float* Vt = Vb + (size_t)(j * 64) * QKVN;
        for (int i = tid; i < 64 * 32; i += 256) {
            int r = i >> 5, c4 = (i & 31) * 4;
            *(float4*)&Ks[r * QP + c4] = *(const float4*)(Kt + (size_t)r * QKVN + c4);
            *(float4*)&Vs[r * VP + c4] = *(const float4*)(Vt + (size_t)r * QKVN + c4);
        }
        __syncthreads();

        // ---- S = Q K^T ----
        float s[4][4];
#pragma unroll
        for (int nf = 0; nf < 4; nf++)
#pragma unroll
            for (int c = 0; c < 4; c++) s[nf][c] = 0.f;

#pragma unroll
        for (int ks = 0; ks < 16; ks++) {
            int k0 = ks * 8;
            unsigned a0 = __float_as_uint(Qs[(m0 + lr)     * QP + k0 + lc]);
            unsigned a1 = __float_as_uint(Qs[(m0 + lr + 8) * QP + k0 + lc]);
            unsigned a2 = __float_as_uint(Qs[(m0 + lr)     * QP + k0 + lc + 4]);
            unsigned a3 = __float_as_uint(Qs[(m0 + lr + 8) * QP + k0 + lc + 4]);
#pragma unroll
            for (int nf = 0; nf < 4; nf++) {
                int n = n0s + nf * 8;
                unsigned b0 = __float_as_uint(Ks[(n + lr) * QP + k0 + lc]);
                unsigned b1 = __float_as_uint(Ks[(n + lr) * QP + k0 + lc + 4]);
                mma_tf32(s[nf], a0, a1, a2, a3, b0, b1);
            }
        }

#pragma unroll
        for (int nf = 0; nf < 4; nf++) {
            int col = n0s + nf * 8 + lc * 2;
            *(float2*)&Sh[(m0 + lr)     * SP + col] = make_float2(s[nf][0], s[nf][1]);
            *(float2*)&Sh[(m0 + lr + 8) * SP + col] = make_float2(s[nf][2], s[nf][3]);
        }
        __syncthreads();

        // ---- parallel softmax: 4 threads/row x 16 cols ----
        {
            int rr  = tid >> 2;
            int seg = tid & 3;
            float* Sr = &Sh[rr * SP];
            bool diag = (j == qt);
            float sv[16];
            float mloc = -3e30f;
#pragma unroll
            for (int c = 0; c < 16; c++) {
                int col = seg * 16 + c;
                float v = (diag && col > rr) ? -3e30f : Sr[col];
                sv[c] = v;
                mloc = fmaxf(mloc, v);
            }
            mloc = fmaxf(mloc, __shfl_xor_sync(0xffffffffu, mloc, 1));
            mloc = fmaxf(mloc, __shfl_xor_sync(0xffffffffu, mloc, 2));
            float mold = rowm[rr];
            float mn = fmaxf(mold, mloc);
            float lloc = 0.f;
#pragma unroll
            for (int c = 0; c < 16; c++) {
                int col = seg * 16 + c;
                float p = __expf(sv[c] - mn);
                lloc += p;
                Sr[col] = __uint_as_float(f2tf32(p));
            }
            lloc += __shfl_xor_sync(0xffffffffu, lloc, 1);
            lloc += __shfl_xor_sync(0xffffffffu, lloc, 2);
            if (seg == 0) {
                float a = __expf(mold - mn);
                rowl[rr] = rowl[rr] * a + lloc;
                rowm[rr] = mn;
                ralp[rr] = a;
            }
        }
        __syncthreads();

        float aL = ralp[m0 + lr], aH = ralp[m0 + 8 + lr];
#pragma unroll
        for (int nf = 0; nf < 8; nf++) {
            o[nf][0] *= aL; o[nf][1] *= aL; o[nf][2] *= aH; o[nf][3] *= aH;
        }

        // ---- O += P V (single pass, tf32 P) ----
#pragma unroll
        for (int ks = 0; ks < 8; ks++) {
            int k0 = ks * 8;
            unsigned h0 = __float_as_uint(Sh[(m0 + lr)     * SP + k0 + lc]);
            unsigned h1 = __float_as_uint(Sh[(m0 + lr + 8) * SP + k0 + lc]);
            unsigned h2 = __float_as_uint(Sh[(m0 + lr)     * SP + k0 + lc + 4]);
            unsigned h3 = __float_as_uint(Sh[(m0 + lr + 8) * SP + k0 + lc + 4]);
#pragma unroll
            for (int nf = 0; nf < 8; nf++) {
                int n = n0d + nf * 8;
                unsigned b0 = __float_as_uint(Vs[(k0 + lc)     * VP + n + lr]);
                unsigned b1 = __float_as_uint(Vs[(k0 + lc + 4) * VP + n + lr]);
                mma_tf32(o[nf], h0, h1, h2, h3, b0, b1);
            }
        }
        __syncthreads();
    }

    // ---- epilogue: 1/l, sigmoid gate, tf32 rounding ----
#pragma unroll
    for (int half = 0; half < 2; half++) {
        int rr = m0 + half * 8 + lr;
        float linv = 1.0f / rowl[rr];
        int grow = qt * 64 + rr;
        const float* gbase = qkv + ((size_t)(b * T_ + grow)) * QKVN + h * 2 * HD_ + HD_;
        unsigned* obase = (unsigned*)(Oout + ((size_t)(b * T_ + grow) * (H_ * HD_)) + h * HD_);
#pragma unroll
        for (int nf = 0; nf < 8; nf++) {
            int d = n0d + nf * 8 + lc * 2;
#pragma unroll
            for (int e = 0; e < 2; e++) {
                float gt = gbase[d + e];
                float sg = 1.0f / (1.0f + __expf(-gt));
                float val = o[nf][half * 2 + e] * linv * sg;
                obase[d + e] = f2tf32(val);
            }
        }
    }
}

// ---------------- launch ----------------
extern "C" void kernel_launch(void* const* d_in, const int* in_sizes, int n_in,
                              void* d_out, int out_size) {
    const float* x    = (const float*)d_in[0];
    const float* w_q  = (const float*)d_in[1];
    const float* w_k  = (const float*)d_in[2];
    const float* w_v  = (const float*)d_in[3];
    const float* w_o  = (const float*)d_in[4];
    const float* qnw  = (const float*)d_in[5];
    const float* knw  = (const float*)d_in[6];
    const float* cs   = (const float*)d_in[7];
    const float* sn   = (const float*)d_in[8];
    float* out = (float*)d_out;

    float *qkv, *q, *attn, *xt, *wqkvt, *wot;
    cudaGetSymbolAddress((void**)&qkv,   g_qkv);
    cudaGetSymbolAddress((void**)&q,     g_q);
    cudaGetSymbolAddress((void**)&attn,  g_attn);
    cudaGetSymbolAddress((void**)&xt,    g_xt);
    cudaGetSymbolAddress((void**)&wqkvt, g_wqkvt);
    cudaGetSymbolAddress((void**)&wot,   g_wot);

    cudaFuncSetAttribute((const void*)flash_tc,
                         cudaFuncAttributeMaxDynamicSharedMemorySize, FLASH_SMEM);
    cudaFuncSetAttribute((const void*)gemm_tf32,
                         cudaFuncAttributeMaxDynamicSharedMemorySize, GEMM_SMEM);

    const int M = B_ * T_;  // 4096

    // tf32 rounding pre-pass; weights land in the fused wqkvt at column offsets
    {
        int n4;
        n4 = (B_ * T_ * D_) / 4;
        cvt_tf32<<<(n4 + 255) / 256, 256>>>(x, xt, n4);
        n4 = (D_ * 2 * H_ * HD_) / 4;
        cvt_tf32_s<<<(n4 + 255) / 256, 256>>>(w_q, wqkvt, (2 * H_ * HD_) / 4, QKVN, 0, n4);
        n4 = (D_ * G_ * HD_) / 4;
        cvt_tf32_s<<<(n4 + 255) / 256, 256>>>(w_k, wqkvt, (G_ * HD_) / 4, QKVN, KOFF, n4);
        cvt_tf32_s<<<(n4 + 255) / 256, 256>>>(w_v, wqkvt, (G_ * HD_) / 4, QKVN, VOFF, n4);
        n4 = (H_ * HD_ * D_) / 4;
        cvt_tf32<<<(n4 + 255) / 256, 256>>>(w_o, wot, n4);
    }

    // fused QKV projection (one GEMM, N=5120)
    gemm_tf32<<<dim3(QKVN / 128, M / 128), 256, GEMM_SMEM>>>(xt, wqkvt, qkv, M, QKVN, D_);

    // norms + rope (emit tf32 bits); V region -> tf32 bits
    qnorm_rope<<<dim3(T_, B_ * H_), 128>>>(qkv, q, qnw, cs, sn);
    knorm_rope<<<dim3(T_, B_ * G_), 128>>>(qkv, knw, cs, sn);
    {
        int n4 = (B_ * T_ * G_ * HD_) / 4;
        cvt_v_region<<<(n4 + 255) / 256, 256>>>(qkv, n4);
    }

    // attention + gate (tf32 tensor cores, single-pass PV)
    flash_tc<<<dim3(T_ / 64, B_ * H_), 256, FLASH_SMEM>>>(q, qkv, attn);

    // output projection
    gemm_tf32<<<dim3(D_ / 128, M / 128), 256, GEMM_SMEM>>>(attn, wot, out, M, D_, D_);
}